// round 1
// baseline (speedup 1.0000x reference)
#include <cuda_runtime.h>
#include <math.h>

#define BB   4
#define SS   2048
#define EMB  512
#define NH   8
#define DK   64
#define BSROWS (BB*SS)   // 8192
#define BH   (BB*NH)     // 32

// Scratch (static __device__ — no allocations allowed)
__device__ float g_q[BH * SS * DK];    // [B,H,S,D]
__device__ float g_k[BH * SS * DK];
__device__ float g_v[BH * SS * DK];
__device__ float g_ctx[BSROWS * EMB];  // [B,S,E]
__device__ float g_x[BSROWS * EMB];    // pre-LN residual sum

// ---------------------------------------------------------------------------
// Generic 512-K GEMM: C = A[M,512] @ W[512,512] + bias (+ resid)
// Block tile 64x64, 256 threads, 4x4 per thread.
// HEAD_MAJOR=1: writes to [B,H,S,D] layout (QKV projections).
// HEAD_MAJOR=0: row-major with residual add (output projection).
// ---------------------------------------------------------------------------
template<int HEAD_MAJOR>
__global__ __launch_bounds__(256) void gemm512_kernel(
    const float* __restrict__ A, const float* __restrict__ W,
    const float* __restrict__ bias, const float* __restrict__ resid,
    float* __restrict__ C)
{
    __shared__ float As[16][64];   // [k][m]
    __shared__ float Ws[16][64];   // [k][n]
    const int t  = threadIdx.x;
    const int tx = t & 15, ty = t >> 4;
    const int row0 = blockIdx.y * 64;
    const int col0 = blockIdx.x * 64;

    const int lr  = t >> 2, lc4 = t & 3;   // A tile loader
    const int wr  = t >> 4, wc4 = t & 15;  // W tile loader

    float acc[4][4] = {};

    for (int kk = 0; kk < 512; kk += 16) {
        float4 av = *(const float4*)(A + (size_t)(row0 + lr) * 512 + kk + lc4 * 4);
        As[lc4*4+0][lr] = av.x; As[lc4*4+1][lr] = av.y;
        As[lc4*4+2][lr] = av.z; As[lc4*4+3][lr] = av.w;
        *(float4*)&Ws[wr][wc4*4] =
            *(const float4*)(W + (size_t)(kk + wr) * 512 + col0 + wc4 * 4);
        __syncthreads();
        #pragma unroll
        for (int k = 0; k < 16; k++) {
            float4 a = *(const float4*)&As[k][ty*4];
            float4 b = *(const float4*)&Ws[k][tx*4];
            acc[0][0] += a.x*b.x; acc[0][1] += a.x*b.y; acc[0][2] += a.x*b.z; acc[0][3] += a.x*b.w;
            acc[1][0] += a.y*b.x; acc[1][1] += a.y*b.y; acc[1][2] += a.y*b.z; acc[1][3] += a.y*b.w;
            acc[2][0] += a.z*b.x; acc[2][1] += a.z*b.y; acc[2][2] += a.z*b.z; acc[2][3] += a.z*b.w;
            acc[3][0] += a.w*b.x; acc[3][1] += a.w*b.y; acc[3][2] += a.w*b.z; acc[3][3] += a.w*b.w;
        }
        __syncthreads();
    }

    #pragma unroll
    for (int i = 0; i < 4; i++) {
        int m = row0 + ty * 4 + i;
        if (HEAD_MAJOR) {
            int b = m >> 11, s = m & 2047;
            #pragma unroll
            for (int j = 0; j < 4; j++) {
                int n = col0 + tx * 4 + j;
                int h = n >> 6, d = n & 63;
                C[(((size_t)(b * NH + h)) * SS + s) * DK + d] = acc[i][j] + bias[n];
            }
        } else {
            int n0 = col0 + tx * 4;
            float4 r = *(const float4*)(resid + (size_t)m * 512 + n0);
            float4 o;
            o.x = acc[i][0] + bias[n0+0] + r.x;
            o.y = acc[i][1] + bias[n0+1] + r.y;
            o.z = acc[i][2] + bias[n0+2] + r.z;
            o.w = acc[i][3] + bias[n0+3] + r.w;
            *(float4*)(C + (size_t)m * 512 + n0) = o;
        }
    }
}

// ---------------------------------------------------------------------------
// Scores: for each (b,h): raw = (q @ k^T) * 1/8, mask -> -1e9, write to attn.
// Block = 64x64 output tile, full K=64 in smem.
// ---------------------------------------------------------------------------
__global__ __launch_bounds__(256) void scores_kernel(
    const unsigned char* __restrict__ mask, float* __restrict__ attn)
{
    __shared__ float Qs[64][64];   // [d][m]
    __shared__ float Ks[64][64];   // [d][n]
    const int t  = threadIdx.x;
    const int tx = t & 15, ty = t >> 4;
    const int bh = blockIdx.z;
    const int b  = bh >> 3;
    const float* qp = g_q + (size_t)bh * SS * DK;
    const float* kp = g_k + (size_t)bh * SS * DK;
    const int r0 = blockIdx.y * 64;
    const int c0 = blockIdx.x * 64;

    const int lr = t >> 2, lc = t & 3;
    #pragma unroll
    for (int i = 0; i < 4; i++) {
        int d0 = (lc + i * 4) * 4;
        float4 v = *(const float4*)(qp + (size_t)(r0 + lr) * DK + d0);
        Qs[d0+0][lr] = v.x; Qs[d0+1][lr] = v.y; Qs[d0+2][lr] = v.z; Qs[d0+3][lr] = v.w;
        float4 w = *(const float4*)(kp + (size_t)(c0 + lr) * DK + d0);
        Ks[d0+0][lr] = w.x; Ks[d0+1][lr] = w.y; Ks[d0+2][lr] = w.z; Ks[d0+3][lr] = w.w;
    }
    __syncthreads();

    float acc[4][4] = {};
    #pragma unroll
    for (int d = 0; d < 64; d++) {
        float4 a = *(const float4*)&Qs[d][ty*4];
        float4 bk = *(const float4*)&Ks[d][tx*4];
        acc[0][0] += a.x*bk.x; acc[0][1] += a.x*bk.y; acc[0][2] += a.x*bk.z; acc[0][3] += a.x*bk.w;
        acc[1][0] += a.y*bk.x; acc[1][1] += a.y*bk.y; acc[1][2] += a.y*bk.z; acc[1][3] += a.y*bk.w;
        acc[2][0] += a.z*bk.x; acc[2][1] += a.z*bk.y; acc[2][2] += a.z*bk.z; acc[2][3] += a.z*bk.w;
        acc[3][0] += a.w*bk.x; acc[3][1] += a.w*bk.y; acc[3][2] += a.w*bk.z; acc[3][3] += a.w*bk.w;
    }

    const float sc = 0.125f;  // 1/sqrt(64)
    #pragma unroll
    for (int i = 0; i < 4; i++) {
        int sq = r0 + ty * 4 + i;
        const unsigned char* mr = mask + ((size_t)b * SS + sq) * SS + c0 + tx * 4;
        float4 o;
        o.x = mr[0] ? -1e9f : acc[i][0] * sc;
        o.y = mr[1] ? -1e9f : acc[i][1] * sc;
        o.z = mr[2] ? -1e9f : acc[i][2] * sc;
        o.w = mr[3] ? -1e9f : acc[i][3] * sc;
        *(float4*)(attn + ((size_t)bh * SS + sq) * SS + c0 + tx * 4) = o;
    }
}

// ---------------------------------------------------------------------------
// Row softmax in place over 2048 elements. One block (256 thr) per row.
// ---------------------------------------------------------------------------
__global__ __launch_bounds__(256) void softmax_kernel(float* __restrict__ attn)
{
    const size_t row = blockIdx.x;
    float* p = attn + row * (size_t)SS;
    const int t = threadIdx.x;
    __shared__ float red[8];

    float4 v0 = ((const float4*)p)[t];
    float4 v1 = ((const float4*)p)[t + 256];

    float m = fmaxf(fmaxf(fmaxf(v0.x, v0.y), fmaxf(v0.z, v0.w)),
                    fmaxf(fmaxf(v1.x, v1.y), fmaxf(v1.z, v1.w)));
    #pragma unroll
    for (int o = 16; o; o >>= 1) m = fmaxf(m, __shfl_xor_sync(0xffffffffu, m, o));
    if ((t & 31) == 0) red[t >> 5] = m;
    __syncthreads();
    m = red[0];
    #pragma unroll
    for (int i = 1; i < 8; i++) m = fmaxf(m, red[i]);
    __syncthreads();

    float4 e0, e1;
    e0.x = __expf(v0.x - m); e0.y = __expf(v0.y - m);
    e0.z = __expf(v0.z - m); e0.w = __expf(v0.w - m);
    e1.x = __expf(v1.x - m); e1.y = __expf(v1.y - m);
    e1.z = __expf(v1.z - m); e1.w = __expf(v1.w - m);

    float s = e0.x + e0.y + e0.z + e0.w + e1.x + e1.y + e1.z + e1.w;
    #pragma unroll
    for (int o = 16; o; o >>= 1) s += __shfl_xor_sync(0xffffffffu, s, o);
    if ((t & 31) == 0) red[t >> 5] = s;
    __syncthreads();
    s = red[0];
    #pragma unroll
    for (int i = 1; i < 8; i++) s += red[i];

    float inv = 1.0f / s;
    e0.x *= inv; e0.y *= inv; e0.z *= inv; e0.w *= inv;
    e1.x *= inv; e1.y *= inv; e1.z *= inv; e1.w *= inv;
    ((float4*)p)[t] = e0;
    ((float4*)p)[t + 256] = e1;
}

// ---------------------------------------------------------------------------
// Context: per (b,h): ctx[S,64] = attn[S,S] @ v[S,64], written to [B,S,E].
// ---------------------------------------------------------------------------
__global__ __launch_bounds__(256) void context_kernel(const float* __restrict__ attn)
{
    __shared__ float Ps[64][68];   // [m][k]
    __shared__ float Vs[64][68];   // [k][n]
    const int t  = threadIdx.x;
    const int tx = t & 15, ty = t >> 4;
    const int bh = blockIdx.y;
    const float* ap = attn + (size_t)bh * SS * SS;
    const float* vp = g_v + (size_t)bh * SS * DK;
    const int r0 = blockIdx.x * 64;

    const int lr = t >> 2, lc = t & 3;
    float acc[4][4] = {};

    for (int kk = 0; kk < SS; kk += 64) {
        #pragma unroll
        for (int i = 0; i < 4; i++) {
            int c = (lc + i * 4) * 4;
            *(float4*)&Ps[lr][c] =
                *(const float4*)(ap + (size_t)(r0 + lr) * SS + kk + c);
            *(float4*)&Vs[lr][c] =
                *(const float4*)(vp + (size_t)(kk + lr) * DK + c);
        }
        __syncthreads();
        #pragma unroll
        for (int k = 0; k < 64; k++) {
            float4 bv = *(const float4*)&Vs[k][tx*4];
            float a0 = Ps[ty*4+0][k], a1 = Ps[ty*4+1][k];
            float a2 = Ps[ty*4+2][k], a3 = Ps[ty*4+3][k];
            acc[0][0] += a0*bv.x; acc[0][1] += a0*bv.y; acc[0][2] += a0*bv.z; acc[0][3] += a0*bv.w;
            acc[1][0] += a1*bv.x; acc[1][1] += a1*bv.y; acc[1][2] += a1*bv.z; acc[1][3] += a1*bv.w;
            acc[2][0] += a2*bv.x; acc[2][1] += a2*bv.y; acc[2][2] += a2*bv.z; acc[2][3] += a2*bv.w;
            acc[3][0] += a3*bv.x; acc[3][1] += a3*bv.y; acc[3][2] += a3*bv.z; acc[3][3] += a3*bv.w;
        }
        __syncthreads();
    }

    const int b = bh >> 3, h = bh & 7;
    #pragma unroll
    for (int i = 0; i < 4; i++) {
        int sq = r0 + ty * 4 + i;
        float4 o = make_float4(acc[i][0], acc[i][1], acc[i][2], acc[i][3]);
        *(float4*)(g_ctx + ((size_t)(b * SS + sq)) * EMB + h * DK + tx * 4) = o;
    }
}

// ---------------------------------------------------------------------------
// LayerNorm over 512: one block (128 thr) per row, float4 per thread.
// ---------------------------------------------------------------------------
__global__ __launch_bounds__(128) void ln_kernel(
    const float* __restrict__ gamma, const float* __restrict__ beta,
    float* __restrict__ out)
{
    const size_t row = blockIdx.x;
    const int t = threadIdx.x;
    const float* x = g_x + row * EMB;
    __shared__ float rs[4], rq[4];

    float4 v = ((const float4*)x)[t];
    float s  = v.x + v.y + v.z + v.w;
    float sq = v.x*v.x + v.y*v.y + v.z*v.z + v.w*v.w;
    #pragma unroll
    for (int o = 16; o; o >>= 1) {
        s  += __shfl_xor_sync(0xffffffffu, s,  o);
        sq += __shfl_xor_sync(0xffffffffu, sq, o);
    }
    if ((t & 31) == 0) { rs[t >> 5] = s; rq[t >> 5] = sq; }
    __syncthreads();
    s  = rs[0] + rs[1] + rs[2] + rs[3];
    sq = rq[0] + rq[1] + rq[2] + rq[3];

    float mu  = s * (1.0f / 512.0f);
    float var = sq * (1.0f / 512.0f) - mu * mu;
    float inv = rsqrtf(var + 1e-5f);

    float4 g = ((const float4*)gamma)[t];
    float4 bb = ((const float4*)beta)[t];
    float4 o;
    o.x = (v.x - mu) * inv * g.x + bb.x;
    o.y = (v.y - mu) * inv * g.y + bb.y;
    o.z = (v.z - mu) * inv * g.z + bb.z;
    o.w = (v.w - mu) * inv * g.w + bb.w;
    ((float4*)(out + row * EMB))[t] = o;
}

// ---------------------------------------------------------------------------
extern "C" void kernel_launch(void* const* d_in, const int* in_sizes, int n_in,
                              void* d_out, int out_size)
{
    const float* Q  = (const float*)d_in[0];
    const float* K  = (const float*)d_in[1];
    const float* V  = (const float*)d_in[2];
    const unsigned char* mask = (const unsigned char*)d_in[3];
    const float* Wq = (const float*)d_in[4];
    const float* bq = (const float*)d_in[5];
    const float* Wk = (const float*)d_in[6];
    const float* bk = (const float*)d_in[7];
    const float* Wv = (const float*)d_in[8];
    const float* bv = (const float*)d_in[9];
    const float* Wo = (const float*)d_in[10];
    const float* bo = (const float*)d_in[11];
    const float* gamma = (const float*)d_in[12];
    const float* beta  = (const float*)d_in[13];

    float* out  = (float*)d_out;
    float* attn = out + (size_t)BSROWS * EMB;   // [B,H,S,S] region

    float *qp, *kp, *vp, *ctxp, *xp;
    cudaGetSymbolAddress((void**)&qp,   g_q);
    cudaGetSymbolAddress((void**)&kp,   g_k);
    cudaGetSymbolAddress((void**)&vp,   g_v);
    cudaGetSymbolAddress((void**)&ctxp, g_ctx);
    cudaGetSymbolAddress((void**)&xp,   g_x);

    dim3 gemm_grid(8, BSROWS / 64);          // 8 x 128
    gemm512_kernel<1><<<gemm_grid, 256>>>(Q, Wq, bq, nullptr, qp);
    gemm512_kernel<1><<<gemm_grid, 256>>>(K, Wk, bk, nullptr, kp);
    gemm512_kernel<1><<<gemm_grid, 256>>>(V, Wv, bv, nullptr, vp);

    dim3 sc_grid(SS / 64, SS / 64, BH);      // 32 x 32 x 32
    scores_kernel<<<sc_grid, 256>>>(mask, attn);

    softmax_kernel<<<BH * SS, 256>>>(attn);  // 65536 rows

    dim3 ctx_grid(SS / 64, BH);              // 32 x 32
    context_kernel<<<ctx_grid, 256>>>(attn);

    gemm512_kernel<0><<<gemm_grid, 256>>>(ctxp, Wo, bo, Q, xp);

    ln_kernel<<<BSROWS, 128>>>(gamma, beta, out);
}

// round 2
// speedup vs baseline: 1.4763x; 1.4763x over previous
#include <cuda_runtime.h>
#include <cuda_bf16.h>
#include <math.h>

#define BB   4
#define SS   2048
#define EMB  512
#define NH   8
#define DK   64
#define BSROWS (BB*SS)   // 8192
#define BH   (BB*NH)     // 32

// Scratch (static __device__ — no allocations allowed)
__device__ __nv_bfloat16 g_qh[BH * SS * DK];
__device__ __nv_bfloat16 g_ql[BH * SS * DK];
__device__ __nv_bfloat16 g_kh[BH * SS * DK];
__device__ __nv_bfloat16 g_kl[BH * SS * DK];
__device__ __nv_bfloat16 g_vh[BH * SS * DK];
__device__ __nv_bfloat16 g_vl[BH * SS * DK];
__device__ float g_ctx[BSROWS * EMB];
__device__ float g_x[BSROWS * EMB];

// ---------------------------------------------------------------------------
// helpers
// ---------------------------------------------------------------------------
__device__ __forceinline__ unsigned sptr(const void* p) {
    return (unsigned)__cvta_generic_to_shared(p);
}
__device__ __forceinline__ void ldsm4(unsigned* r, unsigned a) {
    asm volatile("ldmatrix.sync.aligned.m8n8.x4.shared.b16 {%0,%1,%2,%3}, [%4];"
                 : "=r"(r[0]), "=r"(r[1]), "=r"(r[2]), "=r"(r[3]) : "r"(a));
}
__device__ __forceinline__ void ldsm4t(unsigned* r, unsigned a) {
    asm volatile("ldmatrix.sync.aligned.m8n8.x4.trans.shared.b16 {%0,%1,%2,%3}, [%4];"
                 : "=r"(r[0]), "=r"(r[1]), "=r"(r[2]), "=r"(r[3]) : "r"(a));
}
__device__ __forceinline__ void mma_bf16(float* c, const unsigned* a, const unsigned* b) {
    asm volatile(
        "mma.sync.aligned.m16n8k16.row.col.f32.bf16.bf16.f32 "
        "{%0,%1,%2,%3},{%4,%5,%6,%7},{%8,%9},{%0,%1,%2,%3};"
        : "+f"(c[0]), "+f"(c[1]), "+f"(c[2]), "+f"(c[3])
        : "r"(a[0]), "r"(a[1]), "r"(a[2]), "r"(a[3]), "r"(b[0]), "r"(b[1]));
}
__device__ __forceinline__ void split_pair(float x, float y,
                                           __nv_bfloat162& h2, __nv_bfloat162& l2) {
    __nv_bfloat16 hx = __float2bfloat16_rn(x);
    __nv_bfloat16 hy = __float2bfloat16_rn(y);
    __nv_bfloat16 lx = __float2bfloat16_rn(x - __bfloat162float(hx));
    __nv_bfloat16 ly = __float2bfloat16_rn(y - __bfloat162float(hy));
    h2 = __halves2bfloat162(hx, hy);
    l2 = __halves2bfloat162(lx, ly);
}

// ---------------------------------------------------------------------------
// Projection / out-proj GEMM: C = A[M,512] @ W[512,512] + bias
// Block 128x128, 8 warps (4M x 2N), warp tile 32x64, K-step 32.
// bf16 split (hh + hl + lh), fp32 accumulate.
// OUTPROJ=0: write bf16 hi/lo pairs head-major [B,H,S,D].
// OUTPROJ=1: write fp32 + resid to Of.
// ---------------------------------------------------------------------------
template<int OUTPROJ>
__global__ __launch_bounds__(256) void mma_gemm512(
    const float* __restrict__ A, const float* __restrict__ W,
    const float* __restrict__ bias, const float* __restrict__ resid,
    __nv_bfloat16* __restrict__ Oh, __nv_bfloat16* __restrict__ Ol,
    float* __restrict__ Of)
{
    __shared__ __align__(16) __nv_bfloat16 Ah_s[128][40], Al_s[128][40];
    __shared__ __align__(16) __nv_bfloat16 Bh_s[32][136], Bl_s[32][136];
    const int t = threadIdx.x, lane = t & 31, w = t >> 5;
    const int wm = w & 3, wn = w >> 2;
    const int row0 = blockIdx.y * 128, col0 = blockIdx.x * 128;

    float acc[2][8][4] = {};

    for (int kk = 0; kk < 512; kk += 32) {
        // A tile 128x32 (fp32 -> split)
        {
            int ar = t >> 1, ac = (t & 1) * 16;
            const float* p = A + (size_t)(row0 + ar) * 512 + kk + ac;
            #pragma unroll
            for (int i = 0; i < 16; i += 4) {
                float4 v = *(const float4*)(p + i);
                __nv_bfloat162 h2, l2;
                split_pair(v.x, v.y, h2, l2);
                *(__nv_bfloat162*)&Ah_s[ar][ac + i]     = h2;
                *(__nv_bfloat162*)&Al_s[ar][ac + i]     = l2;
                split_pair(v.z, v.w, h2, l2);
                *(__nv_bfloat162*)&Ah_s[ar][ac + i + 2] = h2;
                *(__nv_bfloat162*)&Al_s[ar][ac + i + 2] = l2;
            }
        }
        // W tile 32x128 (fp32 -> split)
        {
            int br = t >> 3, bc = (t & 7) * 16;
            const float* p = W + (size_t)(kk + br) * 512 + col0 + bc;
            #pragma unroll
            for (int i = 0; i < 16; i += 4) {
                float4 v = *(const float4*)(p + i);
                __nv_bfloat162 h2, l2;
                split_pair(v.x, v.y, h2, l2);
                *(__nv_bfloat162*)&Bh_s[br][bc + i]     = h2;
                *(__nv_bfloat162*)&Bl_s[br][bc + i]     = l2;
                split_pair(v.z, v.w, h2, l2);
                *(__nv_bfloat162*)&Bh_s[br][bc + i + 2] = h2;
                *(__nv_bfloat162*)&Bl_s[br][bc + i + 2] = l2;
            }
        }
        __syncthreads();
        #pragma unroll
        for (int k2 = 0; k2 < 32; k2 += 16) {
            unsigned ah[2][4], al[2][4];
            #pragma unroll
            for (int mi = 0; mi < 2; mi++) {
                int r = wm * 32 + mi * 16 + (lane & 15);
                int c = k2 + ((lane >> 4) << 3);
                ldsm4(ah[mi], sptr(&Ah_s[r][c]));
                ldsm4(al[mi], sptr(&Al_s[r][c]));
            }
            #pragma unroll
            for (int g = 0; g < 4; g++) {
                // W in [k][n] -> trans ldmatrix for col-major B frags (n16 group)
                int kr = k2 + (lane & 7) + (((lane >> 3) & 1) << 3);
                int nc = wn * 64 + g * 16 + ((lane >> 4) << 3);
                unsigned bh_[4], bl_[4];
                ldsm4t(bh_, sptr(&Bh_s[kr][nc]));
                ldsm4t(bl_, sptr(&Bl_s[kr][nc]));
                #pragma unroll
                for (int mi = 0; mi < 2; mi++) {
                    mma_bf16(acc[mi][2*g],   ah[mi], &bh_[0]);
                    mma_bf16(acc[mi][2*g+1], ah[mi], &bh_[2]);
                    mma_bf16(acc[mi][2*g],   ah[mi], &bl_[0]);
                    mma_bf16(acc[mi][2*g+1], ah[mi], &bl_[2]);
                    mma_bf16(acc[mi][2*g],   al[mi], &bh_[0]);
                    mma_bf16(acc[mi][2*g+1], al[mi], &bh_[2]);
                }
            }
        }
        __syncthreads();
    }

    // epilogue
    #pragma unroll
    for (int mi = 0; mi < 2; mi++) {
        #pragma unroll
        for (int nf = 0; nf < 8; nf++) {
            float* c = acc[mi][nf];
            int m = row0 + wm * 32 + mi * 16 + (lane >> 2);
            int n = col0 + wn * 64 + nf * 8 + ((lane & 3) << 1);
            float b0 = bias[n], b1 = bias[n + 1];
            if (OUTPROJ) {
                float2 r = *(const float2*)(resid + (size_t)m * 512 + n);
                float2 o = make_float2(c[0] + b0 + r.x, c[1] + b1 + r.y);
                *(float2*)(Of + (size_t)m * 512 + n) = o;
                r = *(const float2*)(resid + (size_t)(m + 8) * 512 + n);
                o = make_float2(c[2] + b0 + r.x, c[3] + b1 + r.y);
                *(float2*)(Of + (size_t)(m + 8) * 512 + n) = o;
            } else {
                int h = n >> 6, d = n & 63;
                int b = m >> 11, s = m & 2047;
                __nv_bfloat162 h2, l2;
                size_t base = ((size_t)(b * NH + h) * SS + s) * DK + d;
                split_pair(c[0] + b0, c[1] + b1, h2, l2);
                *(__nv_bfloat162*)&Oh[base] = h2;
                *(__nv_bfloat162*)&Ol[base] = l2;
                base += 8 * (size_t)DK;
                split_pair(c[2] + b0, c[3] + b1, h2, l2);
                *(__nv_bfloat162*)&Oh[base] = h2;
                *(__nv_bfloat162*)&Ol[base] = l2;
            }
        }
    }
}

// ---------------------------------------------------------------------------
// Scores: per (b,h) 128x128 tile of q @ k^T * 0.125, masked, fp32 to attn.
// q,k already bf16 hi/lo pairs, K=64 staged in two 32-chunks.
// ---------------------------------------------------------------------------
__global__ __launch_bounds__(256) void mma_scores(
    const unsigned char* __restrict__ mask, float* __restrict__ attn)
{
    __shared__ __align__(16) __nv_bfloat16 Qh[128][40], Ql[128][40];
    __shared__ __align__(16) __nv_bfloat16 Kh[128][40], Kl[128][40];
    const int t = threadIdx.x, lane = t & 31, w = t >> 5;
    const int wm = w & 3, wn = w >> 2;
    const int bh = blockIdx.z, b = bh >> 3;
    const int r0 = blockIdx.y * 128, c0 = blockIdx.x * 128;
    const size_t base = (size_t)bh * SS * DK;

    float acc[2][8][4] = {};

    for (int ks = 0; ks < 64; ks += 32) {
        int ar = t >> 1, au = (t & 1);
        const uint4* s0 = (const uint4*)(g_qh + base + (size_t)(r0 + ar) * 64 + ks);
        const uint4* s1 = (const uint4*)(g_ql + base + (size_t)(r0 + ar) * 64 + ks);
        const uint4* s2 = (const uint4*)(g_kh + base + (size_t)(c0 + ar) * 64 + ks);
        const uint4* s3 = (const uint4*)(g_kl + base + (size_t)(c0 + ar) * 64 + ks);
        *(uint4*)&Qh[ar][au * 16]     = s0[au * 2];
        *(uint4*)&Qh[ar][au * 16 + 8] = s0[au * 2 + 1];
        *(uint4*)&Ql[ar][au * 16]     = s1[au * 2];
        *(uint4*)&Ql[ar][au * 16 + 8] = s1[au * 2 + 1];
        *(uint4*)&Kh[ar][au * 16]     = s2[au * 2];
        *(uint4*)&Kh[ar][au * 16 + 8] = s2[au * 2 + 1];
        *(uint4*)&Kl[ar][au * 16]     = s3[au * 2];
        *(uint4*)&Kl[ar][au * 16 + 8] = s3[au * 2 + 1];
        __syncthreads();
        #pragma unroll
        for (int k2 = 0; k2 < 32; k2 += 16) {
            unsigned ah[2][4], al[2][4];
            #pragma unroll
            for (int mi = 0; mi < 2; mi++) {
                int r = wm * 32 + mi * 16 + (lane & 15);
                int c = k2 + ((lane >> 4) << 3);
                ldsm4(ah[mi], sptr(&Qh[r][c]));
                ldsm4(al[mi], sptr(&Ql[r][c]));
            }
            #pragma unroll
            for (int g = 0; g < 4; g++) {
                // K in [n(sk)][k(d)] -> non-trans B-style load
                int nr = wn * 64 + g * 16 + (lane & 7) + ((lane >> 4) << 3);
                int kc = k2 + (((lane >> 3) & 1) << 3);
                unsigned bh_[4], bl_[4];
                ldsm4(bh_, sptr(&Kh[nr][kc]));
                ldsm4(bl_, sptr(&Kl[nr][kc]));
                #pragma unroll
                for (int mi = 0; mi < 2; mi++) {
                    mma_bf16(acc[mi][2*g],   ah[mi], &bh_[0]);
                    mma_bf16(acc[mi][2*g+1], ah[mi], &bh_[2]);
                    mma_bf16(acc[mi][2*g],   ah[mi], &bl_[0]);
                    mma_bf16(acc[mi][2*g+1], ah[mi], &bl_[2]);
                    mma_bf16(acc[mi][2*g],   al[mi], &bh_[0]);
                    mma_bf16(acc[mi][2*g+1], al[mi], &bh_[2]);
                }
            }
        }
        __syncthreads();
    }

    #pragma unroll
    for (int mi = 0; mi < 2; mi++) {
        #pragma unroll
        for (int nf = 0; nf < 8; nf++) {
            float* c = acc[mi][nf];
            int m = r0 + wm * 32 + mi * 16 + (lane >> 2);
            int n = c0 + wn * 64 + nf * 8 + ((lane & 3) << 1);
            const unsigned char* mp = mask + ((size_t)b * SS + m) * SS + n;
            float2 o;
            o.x = mp[0] ? -1e9f : c[0] * 0.125f;
            o.y = mp[1] ? -1e9f : c[1] * 0.125f;
            *(float2*)(attn + ((size_t)bh * SS + m) * SS + n) = o;
            mp = mask + ((size_t)b * SS + m + 8) * SS + n;
            o.x = mp[0] ? -1e9f : c[2] * 0.125f;
            o.y = mp[1] ? -1e9f : c[3] * 0.125f;
            *(float2*)(attn + ((size_t)bh * SS + m + 8) * SS + n) = o;
        }
    }
}

// ---------------------------------------------------------------------------
// Row softmax in place over 2048 elements.
// ---------------------------------------------------------------------------
__global__ __launch_bounds__(256) void softmax_kernel(float* __restrict__ attn)
{
    const size_t row = blockIdx.x;
    float* p = attn + row * (size_t)SS;
    const int t = threadIdx.x;
    __shared__ float red[8];

    float4 v0 = ((const float4*)p)[t];
    float4 v1 = ((const float4*)p)[t + 256];

    float m = fmaxf(fmaxf(fmaxf(v0.x, v0.y), fmaxf(v0.z, v0.w)),
                    fmaxf(fmaxf(v1.x, v1.y), fmaxf(v1.z, v1.w)));
    #pragma unroll
    for (int o = 16; o; o >>= 1) m = fmaxf(m, __shfl_xor_sync(0xffffffffu, m, o));
    if ((t & 31) == 0) red[t >> 5] = m;
    __syncthreads();
    m = red[0];
    #pragma unroll
    for (int i = 1; i < 8; i++) m = fmaxf(m, red[i]);
    __syncthreads();

    float4 e0, e1;
    e0.x = __expf(v0.x - m); e0.y = __expf(v0.y - m);
    e0.z = __expf(v0.z - m); e0.w = __expf(v0.w - m);
    e1.x = __expf(v1.x - m); e1.y = __expf(v1.y - m);
    e1.z = __expf(v1.z - m); e1.w = __expf(v1.w - m);

    float s = e0.x + e0.y + e0.z + e0.w + e1.x + e1.y + e1.z + e1.w;
    #pragma unroll
    for (int o = 16; o; o >>= 1) s += __shfl_xor_sync(0xffffffffu, s, o);
    if ((t & 31) == 0) red[t >> 5] = s;
    __syncthreads();
    s = red[0];
    #pragma unroll
    for (int i = 1; i < 8; i++) s += red[i];

    float inv = 1.0f / s;
    e0.x *= inv; e0.y *= inv; e0.z *= inv; e0.w *= inv;
    e1.x *= inv; e1.y *= inv; e1.z *= inv; e1.w *= inv;
    ((float4*)p)[t] = e0;
    ((float4*)p)[t + 256] = e1;
}

// ---------------------------------------------------------------------------
// Context: per (b,h) ctx[128,64] tile = attn[128,2048] @ v[2048,64].
// attn fp32 -> split on the fly; v from bf16 pairs. 8 warps, warp tile 16x64.
// ---------------------------------------------------------------------------
__global__ __launch_bounds__(256) void mma_context(
    const float* __restrict__ attn, float* __restrict__ ctx)
{
    __shared__ __align__(16) __nv_bfloat16 Ph[128][40], Pl[128][40];
    __shared__ __align__(16) __nv_bfloat16 Vh[32][72], Vl[32][72];
    const int t = threadIdx.x, lane = t & 31, w = t >> 5;
    const int bh = blockIdx.y, r0 = blockIdx.x * 128;
    const float* ap = attn + (size_t)bh * SS * SS;
    const size_t vbase = (size_t)bh * SS * DK;

    float acc[8][4] = {};

    for (int kk = 0; kk < SS; kk += 32) {
        {
            int ar = t >> 1, ac = (t & 1) * 16;
            const float* p = ap + (size_t)(r0 + ar) * SS + kk + ac;
            #pragma unroll
            for (int i = 0; i < 16; i += 4) {
                float4 v = *(const float4*)(p + i);
                __nv_bfloat162 h2, l2;
                split_pair(v.x, v.y, h2, l2);
                *(__nv_bfloat162*)&Ph[ar][ac + i]     = h2;
                *(__nv_bfloat162*)&Pl[ar][ac + i]     = l2;
                split_pair(v.z, v.w, h2, l2);
                *(__nv_bfloat162*)&Ph[ar][ac + i + 2] = h2;
                *(__nv_bfloat162*)&Pl[ar][ac + i + 2] = l2;
            }
        }
        {
            int idx = t * 8, vr = idx >> 6, vc = idx & 63;
            *(uint4*)&Vh[vr][vc] =
                *(const uint4*)(g_vh + vbase + (size_t)(kk + vr) * 64 + vc);
            *(uint4*)&Vl[vr][vc] =
                *(const uint4*)(g_vl + vbase + (size_t)(kk + vr) * 64 + vc);
        }
        __syncthreads();
        #pragma unroll
        for (int k2 = 0; k2 < 32; k2 += 16) {
            unsigned ah[4], al[4];
            int r = w * 16 + (lane & 15);
            int c = k2 + ((lane >> 4) << 3);
            ldsm4(ah, sptr(&Ph[r][c]));
            ldsm4(al, sptr(&Pl[r][c]));
            #pragma unroll
            for (int g = 0; g < 4; g++) {
                // v in [k(sk)][n(d)] -> trans ldmatrix
                int kr = k2 + (lane & 7) + (((lane >> 3) & 1) << 3);
                int nc = g * 16 + ((lane >> 4) << 3);
                unsigned bh_[4], bl_[4];
                ldsm4t(bh_, sptr(&Vh[kr][nc]));
                ldsm4t(bl_, sptr(&Vl[kr][nc]));
                mma_bf16(acc[2*g],   ah, &bh_[0]);
                mma_bf16(acc[2*g+1], ah, &bh_[2]);
                mma_bf16(acc[2*g],   ah, &bl_[0]);
                mma_bf16(acc[2*g+1], ah, &bl_[2]);
                mma_bf16(acc[2*g],   al, &bh_[0]);
                mma_bf16(acc[2*g+1], al, &bh_[2]);
            }
        }
        __syncthreads();
    }

    const int b = bh >> 3, h = bh & 7;
    #pragma unroll
    for (int nf = 0; nf < 8; nf++) {
        float* c = acc[nf];
        int m = r0 + w * 16 + (lane >> 2);
        int n = nf * 8 + ((lane & 3) << 1);
        *(float2*)(ctx + ((size_t)(b * SS + m)) * EMB + h * DK + n) =
            make_float2(c[0], c[1]);
        *(float2*)(ctx + ((size_t)(b * SS + m + 8)) * EMB + h * DK + n) =
            make_float2(c[2], c[3]);
    }
}

// ---------------------------------------------------------------------------
// LayerNorm over 512.
// ---------------------------------------------------------------------------
__global__ __launch_bounds__(128) void ln_kernel(
    const float* __restrict__ gamma, const float* __restrict__ beta,
    float* __restrict__ out)
{
    const size_t row = blockIdx.x;
    const int t = threadIdx.x;
    const float* x = g_x + row * EMB;
    __shared__ float rs[4], rq[4];

    float4 v = ((const float4*)x)[t];
    float s  = v.x + v.y + v.z + v.w;
    float sq = v.x*v.x + v.y*v.y + v.z*v.z + v.w*v.w;
    #pragma unroll
    for (int o = 16; o; o >>= 1) {
        s  += __shfl_xor_sync(0xffffffffu, s,  o);
        sq += __shfl_xor_sync(0xffffffffu, sq, o);
    }
    if ((t & 31) == 0) { rs[t >> 5] = s; rq[t >> 5] = sq; }
    __syncthreads();
    s  = rs[0] + rs[1] + rs[2] + rs[3];
    sq = rq[0] + rq[1] + rq[2] + rq[3];

    float mu  = s * (1.0f / 512.0f);
    float var = sq * (1.0f / 512.0f) - mu * mu;
    float inv = rsqrtf(var + 1e-5f);

    float4 g = ((const float4*)gamma)[t];
    float4 bb = ((const float4*)beta)[t];
    float4 o;
    o.x = (v.x - mu) * inv * g.x + bb.x;
    o.y = (v.y - mu) * inv * g.y + bb.y;
    o.z = (v.z - mu) * inv * g.z + bb.z;
    o.w = (v.w - mu) * inv * g.w + bb.w;
    ((float4*)(out + row * EMB))[t] = o;
}

// ---------------------------------------------------------------------------
extern "C" void kernel_launch(void* const* d_in, const int* in_sizes, int n_in,
                              void* d_out, int out_size)
{
    const float* Q  = (const float*)d_in[0];
    const float* K  = (const float*)d_in[1];
    const float* V  = (const float*)d_in[2];
    const unsigned char* mask = (const unsigned char*)d_in[3];
    const float* Wq = (const float*)d_in[4];
    const float* bq = (const float*)d_in[5];
    const float* Wk = (const float*)d_in[6];
    const float* bk = (const float*)d_in[7];
    const float* Wv = (const float*)d_in[8];
    const float* bv = (const float*)d_in[9];
    const float* Wo = (const float*)d_in[10];
    const float* bo = (const float*)d_in[11];
    const float* gamma = (const float*)d_in[12];
    const float* beta  = (const float*)d_in[13];

    float* out  = (float*)d_out;
    float* attn = out + (size_t)BSROWS * EMB;

    __nv_bfloat16 *qh, *ql, *kh, *kl, *vh, *vl;
    float *ctxp, *xp;
    cudaGetSymbolAddress((void**)&qh, g_qh);
    cudaGetSymbolAddress((void**)&ql, g_ql);
    cudaGetSymbolAddress((void**)&kh, g_kh);
    cudaGetSymbolAddress((void**)&kl, g_kl);
    cudaGetSymbolAddress((void**)&vh, g_vh);
    cudaGetSymbolAddress((void**)&vl, g_vl);
    cudaGetSymbolAddress((void**)&ctxp, g_ctx);
    cudaGetSymbolAddress((void**)&xp,   g_x);

    dim3 gemm_grid(4, BSROWS / 128);               // 4 x 64
    mma_gemm512<0><<<gemm_grid, 256>>>(Q, Wq, bq, nullptr, qh, ql, nullptr);
    mma_gemm512<0><<<gemm_grid, 256>>>(K, Wk, bk, nullptr, kh, kl, nullptr);
    mma_gemm512<0><<<gemm_grid, 256>>>(V, Wv, bv, nullptr, vh, vl, nullptr);

    dim3 sc_grid(SS / 128, SS / 128, BH);          // 16 x 16 x 32
    mma_scores<<<sc_grid, 256>>>(mask, attn);

    softmax_kernel<<<BH * SS, 256>>>(attn);

    dim3 ctx_grid(SS / 128, BH);                   // 16 x 32
    mma_context<<<ctx_grid, 256>>>(attn, ctxp);

    mma_gemm512<1><<<gemm_grid, 256>>>(ctxp, Wo, bo, Q, nullptr, nullptr, xp);

    ln_kernel<<<BSROWS, 128>>>(gamma, beta, out);
}

// round 3
// speedup vs baseline: 1.5502x; 1.0501x over previous
#include <cuda_runtime.h>
#include <cuda_bf16.h>
#include <math.h>

#define BB   4
#define SS   2048
#define EMB  512
#define NH   8
#define DK   64
#define BSROWS (BB*SS)   // 8192
#define BH   (BB*NH)     // 32

__device__ __nv_bfloat16 g_qh[BH * SS * DK];
__device__ __nv_bfloat16 g_ql[BH * SS * DK];
__device__ __nv_bfloat16 g_kh[BH * SS * DK];
__device__ __nv_bfloat16 g_kl[BH * SS * DK];
__device__ __nv_bfloat16 g_vh[BH * SS * DK];
__device__ __nv_bfloat16 g_vl[BH * SS * DK];
__device__ float g_ctx[BSROWS * EMB];
__device__ float g_x[BSROWS * EMB];

// ---------------------------------------------------------------------------
// helpers
// ---------------------------------------------------------------------------
__device__ __forceinline__ unsigned sptr(const void* p) {
    return (unsigned)__cvta_generic_to_shared(p);
}
__device__ __forceinline__ void ldsm4(unsigned* r, unsigned a) {
    asm volatile("ldmatrix.sync.aligned.m8n8.x4.shared.b16 {%0,%1,%2,%3}, [%4];"
                 : "=r"(r[0]), "=r"(r[1]), "=r"(r[2]), "=r"(r[3]) : "r"(a));
}
__device__ __forceinline__ void ldsm4t(unsigned* r, unsigned a) {
    asm volatile("ldmatrix.sync.aligned.m8n8.x4.trans.shared.b16 {%0,%1,%2,%3}, [%4];"
                 : "=r"(r[0]), "=r"(r[1]), "=r"(r[2]), "=r"(r[3]) : "r"(a));
}
__device__ __forceinline__ void mma_bf16(float* c, const unsigned* a, const unsigned* b) {
    asm volatile(
        "mma.sync.aligned.m16n8k16.row.col.f32.bf16.bf16.f32 "
        "{%0,%1,%2,%3},{%4,%5,%6,%7},{%8,%9},{%0,%1,%2,%3};"
        : "+f"(c[0]), "+f"(c[1]), "+f"(c[2]), "+f"(c[3])
        : "r"(a[0]), "r"(a[1]), "r"(a[2]), "r"(a[3]), "r"(b[0]), "r"(b[1]));
}
__device__ __forceinline__ void split_pair(float x, float y,
                                           __nv_bfloat162& h2, __nv_bfloat162& l2) {
    __nv_bfloat16 hx = __float2bfloat16_rn(x);
    __nv_bfloat16 hy = __float2bfloat16_rn(y);
    __nv_bfloat16 lx = __float2bfloat16_rn(x - __bfloat162float(hx));
    __nv_bfloat16 ly = __float2bfloat16_rn(y - __bfloat162float(hy));
    h2 = __halves2bfloat162(hx, hy);
    l2 = __halves2bfloat162(lx, ly);
}
__device__ __forceinline__ void cp16(unsigned dst, const void* src) {
    asm volatile("cp.async.cg.shared.global [%0], [%1], 16;" :: "r"(dst), "l"(src));
}
__device__ __forceinline__ void cp_commit_wait() {
    asm volatile("cp.async.commit_group;");
    asm volatile("cp.async.wait_group 0;");
}

// ---------------------------------------------------------------------------
// Projection / out-proj GEMM: C = A[M,512] @ W[512,512] + bias (+resid)
// Block 128x64, 256 thr, 8 warps (4m x 2n), warp 32x32, K-step 32.
// ---------------------------------------------------------------------------
template<int OUTPROJ>
__global__ __launch_bounds__(256) void mma_gemm512(
    const float* __restrict__ A, const float* __restrict__ W,
    const float* __restrict__ bias, const float* __restrict__ resid,
    __nv_bfloat16* __restrict__ Oh, __nv_bfloat16* __restrict__ Ol,
    float* __restrict__ Of)
{
    __shared__ __align__(16) __nv_bfloat16 Ah_s[128][40], Al_s[128][40];
    __shared__ __align__(16) __nv_bfloat16 Bh_s[32][72],  Bl_s[32][72];
    const int t = threadIdx.x, lane = t & 31, w = t >> 5;
    const int wm = w & 3, wn = w >> 2;
    const int row0 = blockIdx.y * 128, col0 = blockIdx.x * 64;

    float acc[2][4][4] = {};

    for (int kk = 0; kk < 512; kk += 32) {
        {   // A tile 128x32 fp32 -> split
            int ar = t >> 1, ac = (t & 1) * 16;
            const float* p = A + (size_t)(row0 + ar) * 512 + kk + ac;
            #pragma unroll
            for (int i = 0; i < 16; i += 4) {
                float4 v = *(const float4*)(p + i);
                __nv_bfloat162 h2, l2;
                split_pair(v.x, v.y, h2, l2);
                *(__nv_bfloat162*)&Ah_s[ar][ac + i]     = h2;
                *(__nv_bfloat162*)&Al_s[ar][ac + i]     = l2;
                split_pair(v.z, v.w, h2, l2);
                *(__nv_bfloat162*)&Ah_s[ar][ac + i + 2] = h2;
                *(__nv_bfloat162*)&Al_s[ar][ac + i + 2] = l2;
            }
        }
        {   // W tile 32x64 fp32 -> split
            int br = t >> 3, bc = (t & 7) * 8;
            const float* p = W + (size_t)(kk + br) * 512 + col0 + bc;
            #pragma unroll
            for (int i = 0; i < 8; i += 4) {
                float4 v = *(const float4*)(p + i);
                __nv_bfloat162 h2, l2;
                split_pair(v.x, v.y, h2, l2);
                *(__nv_bfloat162*)&Bh_s[br][bc + i]     = h2;
                *(__nv_bfloat162*)&Bl_s[br][bc + i]     = l2;
                split_pair(v.z, v.w, h2, l2);
                *(__nv_bfloat162*)&Bh_s[br][bc + i + 2] = h2;
                *(__nv_bfloat162*)&Bl_s[br][bc + i + 2] = l2;
            }
        }
        __syncthreads();
        #pragma unroll
        for (int k2 = 0; k2 < 32; k2 += 16) {
            unsigned ah[2][4], al[2][4];
            #pragma unroll
            for (int mi = 0; mi < 2; mi++) {
                int r = wm * 32 + mi * 16 + (lane & 15);
                int c = k2 + ((lane >> 4) << 3);
                ldsm4(ah[mi], sptr(&Ah_s[r][c]));
                ldsm4(al[mi], sptr(&Al_s[r][c]));
            }
            #pragma unroll
            for (int g = 0; g < 2; g++) {
                int kr = k2 + (lane & 7) + (((lane >> 3) & 1) << 3);
                int nc = wn * 32 + g * 16 + ((lane >> 4) << 3);
                unsigned bh_[4], bl_[4];
                ldsm4t(bh_, sptr(&Bh_s[kr][nc]));
                ldsm4t(bl_, sptr(&Bl_s[kr][nc]));
                #pragma unroll
                for (int mi = 0; mi < 2; mi++) {
                    mma_bf16(acc[mi][2*g],   ah[mi], &bh_[0]);
                    mma_bf16(acc[mi][2*g+1], ah[mi], &bh_[2]);
                    mma_bf16(acc[mi][2*g],   ah[mi], &bl_[0]);
                    mma_bf16(acc[mi][2*g+1], ah[mi], &bl_[2]);
                    mma_bf16(acc[mi][2*g],   al[mi], &bh_[0]);
                    mma_bf16(acc[mi][2*g+1], al[mi], &bh_[2]);
                }
            }
        }
        __syncthreads();
    }

    #pragma unroll
    for (int mi = 0; mi < 2; mi++) {
        #pragma unroll
        for (int nf = 0; nf < 4; nf++) {
            float* c = acc[mi][nf];
            int m = row0 + wm * 32 + mi * 16 + (lane >> 2);
            int n = col0 + wn * 32 + nf * 8 + ((lane & 3) << 1);
            float b0 = bias[n], b1 = bias[n + 1];
            if (OUTPROJ) {
                float2 r = *(const float2*)(resid + (size_t)m * 512 + n);
                *(float2*)(Of + (size_t)m * 512 + n) =
                    make_float2(c[0] + b0 + r.x, c[1] + b1 + r.y);
                r = *(const float2*)(resid + (size_t)(m + 8) * 512 + n);
                *(float2*)(Of + (size_t)(m + 8) * 512 + n) =
                    make_float2(c[2] + b0 + r.x, c[3] + b1 + r.y);
            } else {
                int h = n >> 6, d = n & 63;
                int b = m >> 11, s = m & 2047;
                __nv_bfloat162 h2, l2;
                size_t base = ((size_t)(b * NH + h) * SS + s) * DK + d;
                split_pair(c[0] + b0, c[1] + b1, h2, l2);
                *(__nv_bfloat162*)&Oh[base] = h2;
                *(__nv_bfloat162*)&Ol[base] = l2;
                base += 8 * (size_t)DK;
                split_pair(c[2] + b0, c[3] + b1, h2, l2);
                *(__nv_bfloat162*)&Oh[base] = h2;
                *(__nv_bfloat162*)&Ol[base] = l2;
            }
        }
    }
}

// ---------------------------------------------------------------------------
// Scores: per (b,h) 128x128 tile of q @ k^T * 0.125, masked, fp32 to attn.
// 512 thr, 16 warps (4m x 4n), warp 32x32. Full K=64 staged once via cp.async.
// ---------------------------------------------------------------------------
__global__ __launch_bounds__(512) void mma_scores(
    const unsigned char* __restrict__ mask, float* __restrict__ attn)
{
    __shared__ __align__(16) __nv_bfloat16 Qh[128][72], Ql[128][72];
    __shared__ __align__(16) __nv_bfloat16 Kh[128][72], Kl[128][72];
    const int t = threadIdx.x, lane = t & 31, w = t >> 5;
    const int wm = w & 3, wn = w >> 2;
    const int bh = blockIdx.z, b = bh >> 3;
    const int r0 = blockIdx.y * 128, c0 = blockIdx.x * 128;
    const size_t base = (size_t)bh * SS * DK;

    // 4 arrays x 1024 16B-chunks, 8 per thread
    #pragma unroll
    for (int i = 0; i < 8; i++) {
        int chunk = t + i * 512;
        int arr = chunk >> 10, idx = chunk & 1023;
        int r = idx >> 3, c8 = (idx & 7) * 8;
        const __nv_bfloat16* src;
        unsigned dst;
        if (arr == 0)      { src = g_qh + base + (size_t)(r0 + r) * 64 + c8; dst = sptr(&Qh[r][c8]); }
        else if (arr == 1) { src = g_ql + base + (size_t)(r0 + r) * 64 + c8; dst = sptr(&Ql[r][c8]); }
        else if (arr == 2) { src = g_kh + base + (size_t)(c0 + r) * 64 + c8; dst = sptr(&Kh[r][c8]); }
        else               { src = g_kl + base + (size_t)(c0 + r) * 64 + c8; dst = sptr(&Kl[r][c8]); }
        cp16(dst, src);
    }
    cp_commit_wait();
    __syncthreads();

    float acc[2][4][4] = {};
    #pragma unroll
    for (int k2 = 0; k2 < 64; k2 += 16) {
        unsigned ah[2][4], al[2][4];
        #pragma unroll
        for (int mi = 0; mi < 2; mi++) {
            int r = wm * 32 + mi * 16 + (lane & 15);
            int c = k2 + ((lane >> 4) << 3);
            ldsm4(ah[mi], sptr(&Qh[r][c]));
            ldsm4(al[mi], sptr(&Ql[r][c]));
        }
        #pragma unroll
        for (int g = 0; g < 2; g++) {
            int nr = wn * 32 + g * 16 + (lane & 7) + ((lane >> 4) << 3);
            int kc = k2 + (((lane >> 3) & 1) << 3);
            unsigned bh_[4], bl_[4];
            ldsm4(bh_, sptr(&Kh[nr][kc]));
            ldsm4(bl_, sptr(&Kl[nr][kc]));
            #pragma unroll
            for (int mi = 0; mi < 2; mi++) {
                mma_bf16(acc[mi][2*g],   ah[mi], &bh_[0]);
                mma_bf16(acc[mi][2*g+1], ah[mi], &bh_[2]);
                mma_bf16(acc[mi][2*g],   ah[mi], &bl_[0]);
                mma_bf16(acc[mi][2*g+1], ah[mi], &bl_[2]);
                mma_bf16(acc[mi][2*g],   al[mi], &bh_[0]);
                mma_bf16(acc[mi][2*g+1], al[mi], &bh_[2]);
            }
        }
    }

    #pragma unroll
    for (int mi = 0; mi < 2; mi++) {
        #pragma unroll
        for (int nf = 0; nf < 4; nf++) {
            float* c = acc[mi][nf];
            int m = r0 + wm * 32 + mi * 16 + (lane >> 2);
            int n = c0 + wn * 32 + nf * 8 + ((lane & 3) << 1);
            const unsigned char* mp = mask + ((size_t)b * SS + m) * SS + n;
            float2 o;
            o.x = mp[0] ? -1e9f : c[0] * 0.125f;
            o.y = mp[1] ? -1e9f : c[1] * 0.125f;
            *(float2*)(attn + ((size_t)bh * SS + m) * SS + n) = o;
            mp = mask + ((size_t)b * SS + m + 8) * SS + n;
            o.x = mp[0] ? -1e9f : c[2] * 0.125f;
            o.y = mp[1] ? -1e9f : c[3] * 0.125f;
            *(float2*)(attn + ((size_t)bh * SS + m + 8) * SS + n) = o;
        }
    }
}

// ---------------------------------------------------------------------------
// Row softmax in place over 2048 elements.
// ---------------------------------------------------------------------------
__global__ __launch_bounds__(256) void softmax_kernel(float* __restrict__ attn)
{
    const size_t row = blockIdx.x;
    float* p = attn + row * (size_t)SS;
    const int t = threadIdx.x;
    __shared__ float red[8];

    float4 v0 = ((const float4*)p)[t];
    float4 v1 = ((const float4*)p)[t + 256];

    float m = fmaxf(fmaxf(fmaxf(v0.x, v0.y), fmaxf(v0.z, v0.w)),
                    fmaxf(fmaxf(v1.x, v1.y), fmaxf(v1.z, v1.w)));
    #pragma unroll
    for (int o = 16; o; o >>= 1) m = fmaxf(m, __shfl_xor_sync(0xffffffffu, m, o));
    if ((t & 31) == 0) red[t >> 5] = m;
    __syncthreads();
    m = red[0];
    #pragma unroll
    for (int i = 1; i < 8; i++) m = fmaxf(m, red[i]);
    __syncthreads();

    float4 e0, e1;
    e0.x = __expf(v0.x - m); e0.y = __expf(v0.y - m);
    e0.z = __expf(v0.z - m); e0.w = __expf(v0.w - m);
    e1.x = __expf(v1.x - m); e1.y = __expf(v1.y - m);
    e1.z = __expf(v1.z - m); e1.w = __expf(v1.w - m);

    float s = e0.x + e0.y + e0.z + e0.w + e1.x + e1.y + e1.z + e1.w;
    #pragma unroll
    for (int o = 16; o; o >>= 1) s += __shfl_xor_sync(0xffffffffu, s, o);
    if ((t & 31) == 0) red[t >> 5] = s;
    __syncthreads();
    s = red[0];
    #pragma unroll
    for (int i = 1; i < 8; i++) s += red[i];

    float inv = 1.0f / s;
    e0.x *= inv; e0.y *= inv; e0.z *= inv; e0.w *= inv;
    e1.x *= inv; e1.y *= inv; e1.z *= inv; e1.w *= inv;
    ((float4*)p)[t] = e0;
    ((float4*)p)[t + 256] = e1;
}

// ---------------------------------------------------------------------------
// Context: per (b,h) ctx[128,64] = attn[128,2048] @ v[2048,64].
// 256 thr, 8 warps (4m x 2n), warp 32x32, K chunk 64, V via cp.async.
// ---------------------------------------------------------------------------
__global__ __launch_bounds__(256) void mma_context(
    const float* __restrict__ attn, float* __restrict__ ctx)
{
    __shared__ __align__(16) __nv_bfloat16 Ph[128][72], Pl[128][72];
    __shared__ __align__(16) __nv_bfloat16 Vh[64][72],  Vl[64][72];
    const int t = threadIdx.x, lane = t & 31, w = t >> 5;
    const int wm = w & 3, wn = w >> 2;
    const int bh = blockIdx.y, r0 = blockIdx.x * 128;
    const float* ap = attn + (size_t)bh * SS * SS;
    const size_t vbase = (size_t)bh * SS * DK;

    float acc[2][4][4] = {};

    for (int kk = 0; kk < SS; kk += 64) {
        // V chunk 64x64 hi/lo via cp.async: 2 arrays x 512 chunks, 4/thread
        #pragma unroll
        for (int i = 0; i < 4; i++) {
            int chunk = t + i * 256;
            int arr = chunk >> 9, idx = chunk & 511;
            int vr = idx >> 3, vc = (idx & 7) * 8;
            if (arr == 0)
                cp16(sptr(&Vh[vr][vc]), g_vh + vbase + (size_t)(kk + vr) * 64 + vc);
            else
                cp16(sptr(&Vl[vr][vc]), g_vl + vbase + (size_t)(kk + vr) * 64 + vc);
        }
        // P chunk 128x64 fp32 -> split (overlaps with cp.async in flight)
        {
            int pr = t >> 1, pc = (t & 1) * 32;
            const float* p = ap + (size_t)(r0 + pr) * SS + kk + pc;
            #pragma unroll
            for (int i = 0; i < 32; i += 4) {
                float4 v = *(const float4*)(p + i);
                __nv_bfloat162 h2, l2;
                split_pair(v.x, v.y, h2, l2);
                *(__nv_bfloat162*)&Ph[pr][pc + i]     = h2;
                *(__nv_bfloat162*)&Pl[pr][pc + i]     = l2;
                split_pair(v.z, v.w, h2, l2);
                *(__nv_bfloat162*)&Ph[pr][pc + i + 2] = h2;
                *(__nv_bfloat162*)&Pl[pr][pc + i + 2] = l2;
            }
        }
        cp_commit_wait();
        __syncthreads();
        #pragma unroll
        for (int k2 = 0; k2 < 64; k2 += 16) {
            unsigned ah[2][4], al[2][4];
            #pragma unroll
            for (int mi = 0; mi < 2; mi++) {
                int r = wm * 32 + mi * 16 + (lane & 15);
                int c = k2 + ((lane >> 4) << 3);
                ldsm4(ah[mi], sptr(&Ph[r][c]));
                ldsm4(al[mi], sptr(&Pl[r][c]));
            }
            #pragma unroll
            for (int g = 0; g < 2; g++) {
                int kr = k2 + (lane & 7) + (((lane >> 3) & 1) << 3);
                int nc = wn * 32 + g * 16 + ((lane >> 4) << 3);
                unsigned bh_[4], bl_[4];
                ldsm4t(bh_, sptr(&Vh[kr][nc]));
                ldsm4t(bl_, sptr(&Vl[kr][nc]));
                #pragma unroll
                for (int mi = 0; mi < 2; mi++) {
                    mma_bf16(acc[mi][2*g],   ah[mi], &bh_[0]);
                    mma_bf16(acc[mi][2*g+1], ah[mi], &bh_[2]);
                    mma_bf16(acc[mi][2*g],   ah[mi], &bl_[0]);
                    mma_bf16(acc[mi][2*g+1], ah[mi], &bl_[2]);
                    mma_bf16(acc[mi][2*g],   al[mi], &bh_[0]);
                    mma_bf16(acc[mi][2*g+1], al[mi], &bh_[2]);
                }
            }
        }
        __syncthreads();
    }

    const int b = bh >> 3, h = bh & 7;
    #pragma unroll
    for (int mi = 0; mi < 2; mi++) {
        #pragma unroll
        for (int nf = 0; nf < 4; nf++) {
            float* c = acc[mi][nf];
            int m = r0 + wm * 32 + mi * 16 + (lane >> 2);
            int n = wn * 32 + nf * 8 + ((lane & 3) << 1);
            *(float2*)(ctx + ((size_t)(b * SS + m)) * EMB + h * DK + n) =
                make_float2(c[0], c[1]);
            *(float2*)(ctx + ((size_t)(b * SS + m + 8)) * EMB + h * DK + n) =
                make_float2(c[2], c[3]);
        }
    }
}

// ---------------------------------------------------------------------------
// LayerNorm over 512.
// ---------------------------------------------------------------------------
__global__ __launch_bounds__(128) void ln_kernel(
    const float* __restrict__ gamma, const float* __restrict__ beta,
    float* __restrict__ out)
{
    const size_t row = blockIdx.x;
    const int t = threadIdx.x;
    const float* x = g_x + row * EMB;
    __shared__ float rs[4], rq[4];

    float4 v = ((const float4*)x)[t];
    float s  = v.x + v.y + v.z + v.w;
    float sq = v.x*v.x + v.y*v.y + v.z*v.z + v.w*v.w;
    #pragma unroll
    for (int o = 16; o; o >>= 1) {
        s  += __shfl_xor_sync(0xffffffffu, s,  o);
        sq += __shfl_xor_sync(0xffffffffu, sq, o);
    }
    if ((t & 31) == 0) { rs[t >> 5] = s; rq[t >> 5] = sq; }
    __syncthreads();
    s  = rs[0] + rs[1] + rs[2] + rs[3];
    sq = rq[0] + rq[1] + rq[2] + rq[3];

    float mu  = s * (1.0f / 512.0f);
    float var = sq * (1.0f / 512.0f) - mu * mu;
    float inv = rsqrtf(var + 1e-5f);

    float4 g = ((const float4*)gamma)[t];
    float4 bb = ((const float4*)beta)[t];
    float4 o;
    o.x = (v.x - mu) * inv * g.x + bb.x;
    o.y = (v.y - mu) * inv * g.y + bb.y;
    o.z = (v.z - mu) * inv * g.z + bb.z;
    o.w = (v.w - mu) * inv * g.w + bb.w;
    ((float4*)(out + row * EMB))[t] = o;
}

// ---------------------------------------------------------------------------
extern "C" void kernel_launch(void* const* d_in, const int* in_sizes, int n_in,
                              void* d_out, int out_size)
{
    const float* Q  = (const float*)d_in[0];
    const float* K  = (const float*)d_in[1];
    const float* V  = (const float*)d_in[2];
    const unsigned char* mask = (const unsigned char*)d_in[3];
    const float* Wq = (const float*)d_in[4];
    const float* bq = (const float*)d_in[5];
    const float* Wk = (const float*)d_in[6];
    const float* bk = (const float*)d_in[7];
    const float* Wv = (const float*)d_in[8];
    const float* bv = (const float*)d_in[9];
    const float* Wo = (const float*)d_in[10];
    const float* bo = (const float*)d_in[11];
    const float* gamma = (const float*)d_in[12];
    const float* beta  = (const float*)d_in[13];

    float* out  = (float*)d_out;
    float* attn = out + (size_t)BSROWS * EMB;

    __nv_bfloat16 *qh, *ql, *kh, *kl, *vh, *vl;
    float *ctxp, *xp;
    cudaGetSymbolAddress((void**)&qh, g_qh);
    cudaGetSymbolAddress((void**)&ql, g_ql);
    cudaGetSymbolAddress((void**)&kh, g_kh);
    cudaGetSymbolAddress((void**)&kl, g_kl);
    cudaGetSymbolAddress((void**)&vh, g_vh);
    cudaGetSymbolAddress((void**)&vl, g_vl);
    cudaGetSymbolAddress((void**)&ctxp, g_ctx);
    cudaGetSymbolAddress((void**)&xp,   g_x);

    dim3 gemm_grid(EMB / 64, BSROWS / 128);        // 8 x 64
    mma_gemm512<0><<<gemm_grid, 256>>>(Q, Wq, bq, nullptr, qh, ql, nullptr);
    mma_gemm512<0><<<gemm_grid, 256>>>(K, Wk, bk, nullptr, kh, kl, nullptr);
    mma_gemm512<0><<<gemm_grid, 256>>>(V, Wv, bv, nullptr, vh, vl, nullptr);

    dim3 sc_grid(SS / 128, SS / 128, BH);          // 16 x 16 x 32
    mma_scores<<<sc_grid, 512>>>(mask, attn);

    softmax_kernel<<<BH * SS, 256>>>(attn);

    dim3 ctx_grid(SS / 128, BH);                   // 16 x 32
    mma_context<<<ctx_grid, 256>>>(attn, ctxp);

    mma_gemm512<1><<<gemm_grid, 256>>>(ctxp, Wo, bo, Q, nullptr, nullptr, xp);

    ln_kernel<<<BSROWS, 128>>>(gamma, beta, out);
}

// round 5
// speedup vs baseline: 1.6523x; 1.0659x over previous
#include <cuda_runtime.h>
#include <cuda_bf16.h>
#include <math.h>

#define BB   4
#define SS   2048
#define EMB  512
#define NH   8
#define DK   64
#define BSROWS (BB*SS)   // 8192
#define BH   (BB*NH)     // 32

__device__ __nv_bfloat16 g_qh[BH * SS * DK];
__device__ __nv_bfloat16 g_ql[BH * SS * DK];
__device__ __nv_bfloat16 g_kh[BH * SS * DK];
__device__ __nv_bfloat16 g_kl[BH * SS * DK];
__device__ __nv_bfloat16 g_vh[BH * SS * DK];
__device__ __nv_bfloat16 g_vl[BH * SS * DK];
__device__ float g_ctx[BSROWS * EMB];
__device__ float g_x[BSROWS * EMB];

// ---------------------------------------------------------------------------
// helpers
// ---------------------------------------------------------------------------
__device__ __forceinline__ unsigned sptr(const void* p) {
    return (unsigned)__cvta_generic_to_shared(p);
}
__device__ __forceinline__ void ldsm4(unsigned* r, unsigned a) {
    asm volatile("ldmatrix.sync.aligned.m8n8.x4.shared.b16 {%0,%1,%2,%3}, [%4];"
                 : "=r"(r[0]), "=r"(r[1]), "=r"(r[2]), "=r"(r[3]) : "r"(a));
}
__device__ __forceinline__ void ldsm4t(unsigned* r, unsigned a) {
    asm volatile("ldmatrix.sync.aligned.m8n8.x4.trans.shared.b16 {%0,%1,%2,%3}, [%4];"
                 : "=r"(r[0]), "=r"(r[1]), "=r"(r[2]), "=r"(r[3]) : "r"(a));
}
__device__ __forceinline__ void mma_bf16(float* c, const unsigned* a, const unsigned* b) {
    asm volatile(
        "mma.sync.aligned.m16n8k16.row.col.f32.bf16.bf16.f32 "
        "{%0,%1,%2,%3},{%4,%5,%6,%7},{%8,%9},{%0,%1,%2,%3};"
        : "+f"(c[0]), "+f"(c[1]), "+f"(c[2]), "+f"(c[3])
        : "r"(a[0]), "r"(a[1]), "r"(a[2]), "r"(a[3]), "r"(b[0]), "r"(b[1]));
}
__device__ __forceinline__ void split_pair(float x, float y,
                                           __nv_bfloat162& h2, __nv_bfloat162& l2) {
    __nv_bfloat16 hx = __float2bfloat16_rn(x);
    __nv_bfloat16 hy = __float2bfloat16_rn(y);
    __nv_bfloat16 lx = __float2bfloat16_rn(x - __bfloat162float(hx));
    __nv_bfloat16 ly = __float2bfloat16_rn(y - __bfloat162float(hy));
    h2 = __halves2bfloat162(hx, hy);
    l2 = __halves2bfloat162(lx, ly);
}
__device__ __forceinline__ void cp16(unsigned dst, const void* src) {
    asm volatile("cp.async.cg.shared.global [%0], [%1], 16;" :: "r"(dst), "l"(src));
}
__device__ __forceinline__ void cp_commit_wait() {
    asm volatile("cp.async.commit_group;");
    asm volatile("cp.async.wait_group 0;");
}

// ---------------------------------------------------------------------------
// Scores: per (b,h) 128x64 tile of q @ k^T * 0.125, masked, fp32 to attn.
// 256 thr, 8 warps (4m x 2n), warp 32x32. Full K=64 staged once via cp.async.
// 3 CTAs/SM (regs <= 83) so independent CTAs overlap load/mma/epilogue.
// ---------------------------------------------------------------------------
#define SC_QH 0
#define SC_QL 18432
#define SC_KH 36864
#define SC_KL 46080
#define SC_SMEM 55296

__global__ __launch_bounds__(256, 3) void mma_scores(
    const unsigned char* __restrict__ mask, float* __restrict__ attn)
{
    extern __shared__ __align__(16) char smem_raw[];
    __nv_bfloat16 (*Qh)[72] = (__nv_bfloat16(*)[72])(smem_raw + SC_QH);
    __nv_bfloat16 (*Ql)[72] = (__nv_bfloat16(*)[72])(smem_raw + SC_QL);
    __nv_bfloat16 (*Kh)[72] = (__nv_bfloat16(*)[72])(smem_raw + SC_KH);
    __nv_bfloat16 (*Kl)[72] = (__nv_bfloat16(*)[72])(smem_raw + SC_KL);

    const int t = threadIdx.x, lane = t & 31, w = t >> 5;
    const int wm = w & 3, wn = w >> 2;
    const int bh = blockIdx.z, b = bh >> 3;
    const int r0 = blockIdx.y * 128, c0 = blockIdx.x * 64;
    const size_t base = (size_t)bh * SS * DK;

    // Q: 2 arrays x 1024 chunks (128 rows x 8); K: 2 arrays x 512 chunks (64 rows x 8)
    #pragma unroll
    for (int i = 0; i < 12; i++) {
        int ch = t + i * 256;
        if (ch < 1024) {
            int r = ch >> 3, c8 = (ch & 7) * 8;
            cp16(sptr(&Qh[r][c8]), g_qh + base + (size_t)(r0 + r) * 64 + c8);
        } else if (ch < 2048) {
            int idx = ch - 1024, r = idx >> 3, c8 = (idx & 7) * 8;
            cp16(sptr(&Ql[r][c8]), g_ql + base + (size_t)(r0 + r) * 64 + c8);
        } else if (ch < 2560) {
            int idx = ch - 2048, r = idx >> 3, c8 = (idx & 7) * 8;
            cp16(sptr(&Kh[r][c8]), g_kh + base + (size_t)(c0 + r) * 64 + c8);
        } else {
            int idx = ch - 2560, r = idx >> 3, c8 = (idx & 7) * 8;
            cp16(sptr(&Kl[r][c8]), g_kl + base + (size_t)(c0 + r) * 64 + c8);
        }
    }
    cp_commit_wait();
    __syncthreads();

    float acc[2][4][4] = {};
    #pragma unroll
    for (int k2 = 0; k2 < 64; k2 += 16) {
        unsigned ah[2][4], al[2][4];
        #pragma unroll
        for (int mi = 0; mi < 2; mi++) {
            int r = wm * 32 + mi * 16 + (lane & 15);
            int c = k2 + ((lane >> 4) << 3);
            ldsm4(ah[mi], sptr(&Qh[r][c]));
            ldsm4(al[mi], sptr(&Ql[r][c]));
        }
        #pragma unroll
        for (int g = 0; g < 2; g++) {
            int nr = wn * 32 + g * 16 + (lane & 7) + ((lane >> 4) << 3);
            int kc = k2 + (((lane >> 3) & 1) << 3);
            unsigned bh_[4], bl_[4];
            ldsm4(bh_, sptr(&Kh[nr][kc]));
            ldsm4(bl_, sptr(&Kl[nr][kc]));
            #pragma unroll
            for (int mi = 0; mi < 2; mi++) {
                mma_bf16(acc[mi][2*g],   ah[mi], &bh_[0]);
                mma_bf16(acc[mi][2*g+1], ah[mi], &bh_[2]);
                mma_bf16(acc[mi][2*g],   ah[mi], &bl_[0]);
                mma_bf16(acc[mi][2*g+1], ah[mi], &bl_[2]);
                mma_bf16(acc[mi][2*g],   al[mi], &bh_[0]);
                mma_bf16(acc[mi][2*g+1], al[mi], &bh_[2]);
            }
        }
    }

    #pragma unroll
    for (int mi = 0; mi < 2; mi++) {
        #pragma unroll
        for (int nf = 0; nf < 4; nf++) {
            float* c = acc[mi][nf];
            int m = r0 + wm * 32 + mi * 16 + (lane >> 2);
            int n = c0 + wn * 32 + nf * 8 + ((lane & 3) << 1);
            const unsigned char* mp = mask + ((size_t)b * SS + m) * SS + n;
            float2 o;
            o.x = mp[0] ? -1e9f : c[0] * 0.125f;
            o.y = mp[1] ? -1e9f : c[1] * 0.125f;
            *(float2*)(attn + ((size_t)bh * SS + m) * SS + n) = o;
            mp = mask + ((size_t)b * SS + m + 8) * SS + n;
            o.x = mp[0] ? -1e9f : c[2] * 0.125f;
            o.y = mp[1] ? -1e9f : c[3] * 0.125f;
            *(float2*)(attn + ((size_t)bh * SS + m + 8) * SS + n) = o;
        }
    }
}

// ---------------------------------------------------------------------------
// Projection / out-proj GEMM: C = A[M,512] @ W[512,512] + bias (+resid)
// Block 128x64, 256 thr, 8 warps (4m x 2n), warp 32x32, K-step 32.
// ---------------------------------------------------------------------------
template<int OUTPROJ>
__global__ __launch_bounds__(256, 3) void mma_gemm512(
    const float* __restrict__ A, const float* __restrict__ W,
    const float* __restrict__ bias, const float* __restrict__ resid,
    __nv_bfloat16* __restrict__ Oh, __nv_bfloat16* __restrict__ Ol,
    float* __restrict__ Of)
{
    __shared__ __align__(16) __nv_bfloat16 Ah_s[128][40], Al_s[128][40];
    __shared__ __align__(16) __nv_bfloat16 Bh_s[32][72],  Bl_s[32][72];
    const int t = threadIdx.x, lane = t & 31, w = t >> 5;
    const int wm = w & 3, wn = w >> 2;
    const int row0 = blockIdx.y * 128, col0 = blockIdx.x * 64;

    float acc[2][4][4] = {};

    for (int kk = 0; kk < 512; kk += 32) {
        {
            int ar = t >> 1, ac = (t & 1) * 16;
            const float* p = A + (size_t)(row0 + ar) * 512 + kk + ac;
            #pragma unroll
            for (int i = 0; i < 16; i += 4) {
                float4 v = *(const float4*)(p + i);
                __nv_bfloat162 h2, l2;
                split_pair(v.x, v.y, h2, l2);
                *(__nv_bfloat162*)&Ah_s[ar][ac + i]     = h2;
                *(__nv_bfloat162*)&Al_s[ar][ac + i]     = l2;
                split_pair(v.z, v.w, h2, l2);
                *(__nv_bfloat162*)&Ah_s[ar][ac + i + 2] = h2;
                *(__nv_bfloat162*)&Al_s[ar][ac + i + 2] = l2;
            }
        }
        {
            int br = t >> 3, bc = (t & 7) * 8;
            const float* p = W + (size_t)(kk + br) * 512 + col0 + bc;
            #pragma unroll
            for (int i = 0; i < 8; i += 4) {
                float4 v = *(const float4*)(p + i);
                __nv_bfloat162 h2, l2;
                split_pair(v.x, v.y, h2, l2);
                *(__nv_bfloat162*)&Bh_s[br][bc + i]     = h2;
                *(__nv_bfloat162*)&Bl_s[br][bc + i]     = l2;
                split_pair(v.z, v.w, h2, l2);
                *(__nv_bfloat162*)&Bh_s[br][bc + i + 2] = h2;
                *(__nv_bfloat162*)&Bl_s[br][bc + i + 2] = l2;
            }
        }
        __syncthreads();
        #pragma unroll
        for (int k2 = 0; k2 < 32; k2 += 16) {
            unsigned ah[2][4], al[2][4];
            #pragma unroll
            for (int mi = 0; mi < 2; mi++) {
                int r = wm * 32 + mi * 16 + (lane & 15);
                int c = k2 + ((lane >> 4) << 3);
                ldsm4(ah[mi], sptr(&Ah_s[r][c]));
                ldsm4(al[mi], sptr(&Al_s[r][c]));
            }
            #pragma unroll
            for (int g = 0; g < 2; g++) {
                int kr = k2 + (lane & 7) + (((lane >> 3) & 1) << 3);
                int nc = wn * 32 + g * 16 + ((lane >> 4) << 3);
                unsigned bh_[4], bl_[4];
                ldsm4t(bh_, sptr(&Bh_s[kr][nc]));
                ldsm4t(bl_, sptr(&Bl_s[kr][nc]));
                #pragma unroll
                for (int mi = 0; mi < 2; mi++) {
                    mma_bf16(acc[mi][2*g],   ah[mi], &bh_[0]);
                    mma_bf16(acc[mi][2*g+1], ah[mi], &bh_[2]);
                    mma_bf16(acc[mi][2*g],   ah[mi], &bl_[0]);
                    mma_bf16(acc[mi][2*g+1], ah[mi], &bl_[2]);
                    mma_bf16(acc[mi][2*g],   al[mi], &bh_[0]);
                    mma_bf16(acc[mi][2*g+1], al[mi], &bh_[2]);
                }
            }
        }
        __syncthreads();
    }

    #pragma unroll
    for (int mi = 0; mi < 2; mi++) {
        #pragma unroll
        for (int nf = 0; nf < 4; nf++) {
            float* c = acc[mi][nf];
            int m = row0 + wm * 32 + mi * 16 + (lane >> 2);
            int n = col0 + wn * 32 + nf * 8 + ((lane & 3) << 1);
            float b0 = bias[n], b1 = bias[n + 1];
            if (OUTPROJ) {
                float2 r = *(const float2*)(resid + (size_t)m * 512 + n);
                *(float2*)(Of + (size_t)m * 512 + n) =
                    make_float2(c[0] + b0 + r.x, c[1] + b1 + r.y);
                r = *(const float2*)(resid + (size_t)(m + 8) * 512 + n);
                *(float2*)(Of + (size_t)(m + 8) * 512 + n) =
                    make_float2(c[2] + b0 + r.x, c[3] + b1 + r.y);
            } else {
                int h = n >> 6, d = n & 63;
                int b = m >> 11, s = m & 2047;
                __nv_bfloat162 h2, l2;
                size_t base = ((size_t)(b * NH + h) * SS + s) * DK + d;
                split_pair(c[0] + b0, c[1] + b1, h2, l2);
                *(__nv_bfloat162*)&Oh[base] = h2;
                *(__nv_bfloat162*)&Ol[base] = l2;
                base += 8 * (size_t)DK;
                split_pair(c[2] + b0, c[3] + b1, h2, l2);
                *(__nv_bfloat162*)&Oh[base] = h2;
                *(__nv_bfloat162*)&Ol[base] = l2;
            }
        }
    }
}

// ---------------------------------------------------------------------------
// Row softmax in place over 2048 elements.
// ---------------------------------------------------------------------------
__global__ __launch_bounds__(256) void softmax_kernel(float* __restrict__ attn)
{
    const size_t row = blockIdx.x;
    float* p = attn + row * (size_t)SS;
    const int t = threadIdx.x;
    __shared__ float red[8];

    float4 v0 = ((const float4*)p)[t];
    float4 v1 = ((const float4*)p)[t + 256];

    float m = fmaxf(fmaxf(fmaxf(v0.x, v0.y), fmaxf(v0.z, v0.w)),
                    fmaxf(fmaxf(v1.x, v1.y), fmaxf(v1.z, v1.w)));
    #pragma unroll
    for (int o = 16; o; o >>= 1) m = fmaxf(m, __shfl_xor_sync(0xffffffffu, m, o));
    if ((t & 31) == 0) red[t >> 5] = m;
    __syncthreads();
    m = red[0];
    #pragma unroll
    for (int i = 1; i < 8; i++) m = fmaxf(m, red[i]);
    __syncthreads();

    float4 e0, e1;
    e0.x = __expf(v0.x - m); e0.y = __expf(v0.y - m);
    e0.z = __expf(v0.z - m); e0.w = __expf(v0.w - m);
    e1.x = __expf(v1.x - m); e1.y = __expf(v1.y - m);
    e1.z = __expf(v1.z - m); e1.w = __expf(v1.w - m);

    float s = e0.x + e0.y + e0.z + e0.w + e1.x + e1.y + e1.z + e1.w;
    #pragma unroll
    for (int o = 16; o; o >>= 1) s += __shfl_xor_sync(0xffffffffu, s, o);
    if ((t & 31) == 0) red[t >> 5] = s;
    __syncthreads();
    s = red[0];
    #pragma unroll
    for (int i = 1; i < 8; i++) s += red[i];

    float inv = 1.0f / s;
    e0.x *= inv; e0.y *= inv; e0.z *= inv; e0.w *= inv;
    e1.x *= inv; e1.y *= inv; e1.z *= inv; e1.w *= inv;
    ((float4*)p)[t] = e0;
    ((float4*)p)[t + 256] = e1;
}

// ---------------------------------------------------------------------------
// Context: per (b,h) ctx[128,64] = attn[128,2048] @ v[2048,64].
// 256 thr, 8 warps (4m x 2n), warp 32x32, K chunk 64, V via cp.async.
// ---------------------------------------------------------------------------
__global__ __launch_bounds__(256, 3) void mma_context(
    const float* __restrict__ attn, float* __restrict__ ctx)
{
    __shared__ __align__(16) __nv_bfloat16 Ph[128][72], Pl[128][72];
    __shared__ __align__(16) __nv_bfloat16 Vh[64][72],  Vl[64][72];
    const int t = threadIdx.x, lane = t & 31, w = t >> 5;
    const int wm = w & 3, wn = w >> 2;
    const int bh = blockIdx.y, r0 = blockIdx.x * 128;
    const float* ap = attn + (size_t)bh * SS * SS;
    const size_t vbase = (size_t)bh * SS * DK;

    float acc[2][4][4] = {};

    for (int kk = 0; kk < SS; kk += 64) {
        #pragma unroll
        for (int i = 0; i < 4; i++) {
            int chunk = t + i * 256;
            int arr = chunk >> 9, idx = chunk & 511;
            int vr = idx >> 3, vc = (idx & 7) * 8;
            if (arr == 0)
                cp16(sptr(&Vh[vr][vc]), g_vh + vbase + (size_t)(kk + vr) * 64 + vc);
            else
                cp16(sptr(&Vl[vr][vc]), g_vl + vbase + (size_t)(kk + vr) * 64 + vc);
        }
        {
            int pr = t >> 1, pc = (t & 1) * 32;
            const float* p = ap + (size_t)(r0 + pr) * SS + kk + pc;
            #pragma unroll
            for (int i = 0; i < 32; i += 4) {
                float4 v = *(const float4*)(p + i);
                __nv_bfloat162 h2, l2;
                split_pair(v.x, v.y, h2, l2);
                *(__nv_bfloat162*)&Ph[pr][pc + i]     = h2;
                *(__nv_bfloat162*)&Pl[pr][pc + i]     = l2;
                split_pair(v.z, v.w, h2, l2);
                *(__nv_bfloat162*)&Ph[pr][pc + i + 2] = h2;
                *(__nv_bfloat162*)&Pl[pr][pc + i + 2] = l2;
            }
        }
        cp_commit_wait();
        __syncthreads();
        #pragma unroll
        for (int k2 = 0; k2 < 64; k2 += 16) {
            unsigned ah[2][4], al[2][4];
            #pragma unroll
            for (int mi = 0; mi < 2; mi++) {
                int r = wm * 32 + mi * 16 + (lane & 15);
                int c = k2 + ((lane >> 4) << 3);
                ldsm4(ah[mi], sptr(&Ph[r][c]));
                ldsm4(al[mi], sptr(&Pl[r][c]));
            }
            #pragma unroll
            for (int g = 0; g < 2; g++) {
                int kr = k2 + (lane & 7) + (((lane >> 3) & 1) << 3);
                int nc = wn * 32 + g * 16 + ((lane >> 4) << 3);
                unsigned bh_[4], bl_[4];
                ldsm4t(bh_, sptr(&Vh[kr][nc]));
                ldsm4t(bl_, sptr(&Vl[kr][nc]));
                #pragma unroll
                for (int mi = 0; mi < 2; mi++) {
                    mma_bf16(acc[mi][2*g],   ah[mi], &bh_[0]);
                    mma_bf16(acc[mi][2*g+1], ah[mi], &bh_[2]);
                    mma_bf16(acc[mi][2*g],   ah[mi], &bl_[0]);
                    mma_bf16(acc[mi][2*g+1], ah[mi], &bl_[2]);
                    mma_bf16(acc[mi][2*g],   al[mi], &bh_[0]);
                    mma_bf16(acc[mi][2*g+1], al[mi], &bh_[2]);
                }
            }
        }
        __syncthreads();
    }

    const int b = bh >> 3, h = bh & 7;
    #pragma unroll
    for (int mi = 0; mi < 2; mi++) {
        #pragma unroll
        for (int nf = 0; nf < 4; nf++) {
            float* c = acc[mi][nf];
            int m = r0 + wm * 32 + mi * 16 + (lane >> 2);
            int n = wn * 32 + nf * 8 + ((lane & 3) << 1);
            *(float2*)(ctx + ((size_t)(b * SS + m)) * EMB + h * DK + n) =
                make_float2(c[0], c[1]);
            *(float2*)(ctx + ((size_t)(b * SS + m + 8)) * EMB + h * DK + n) =
                make_float2(c[2], c[3]);
        }
    }
}

// ---------------------------------------------------------------------------
// LayerNorm over 512.
// ---------------------------------------------------------------------------
__global__ __launch_bounds__(128) void ln_kernel(
    const float* __restrict__ gamma, const float* __restrict__ beta,
    float* __restrict__ out)
{
    const size_t row = blockIdx.x;
    const int t = threadIdx.x;
    const float* x = g_x + row * EMB;
    __shared__ float rs[4], rq[4];

    float4 v = ((const float4*)x)[t];
    float s  = v.x + v.y + v.z + v.w;
    float sq = v.x*v.x + v.y*v.y + v.z*v.z + v.w*v.w;
    #pragma unroll
    for (int o = 16; o; o >>= 1) {
        s  += __shfl_xor_sync(0xffffffffu, s,  o);
        sq += __shfl_xor_sync(0xffffffffu, sq, o);
    }
    if ((t & 31) == 0) { rs[t >> 5] = s; rq[t >> 5] = sq; }
    __syncthreads();
    s  = rs[0] + rs[1] + rs[2] + rs[3];
    sq = rq[0] + rq[1] + rq[2] + rq[3];

    float mu  = s * (1.0f / 512.0f);
    float var = sq * (1.0f / 512.0f) - mu * mu;
    float inv = rsqrtf(var + 1e-5f);

    float4 g = ((const float4*)gamma)[t];
    float4 bb = ((const float4*)beta)[t];
    float4 o;
    o.x = (v.x - mu) * inv * g.x + bb.x;
    o.y = (v.y - mu) * inv * g.y + bb.y;
    o.z = (v.z - mu) * inv * g.z + bb.z;
    o.w = (v.w - mu) * inv * g.w + bb.w;
    ((float4*)(out + row * EMB))[t] = o;
}

// ---------------------------------------------------------------------------
extern "C" void kernel_launch(void* const* d_in, const int* in_sizes, int n_in,
                              void* d_out, int out_size)
{
    const float* Q  = (const float*)d_in[0];
    const float* K  = (const float*)d_in[1];
    const float* V  = (const float*)d_in[2];
    const unsigned char* mask = (const unsigned char*)d_in[3];
    const float* Wq = (const float*)d_in[4];
    const float* bq = (const float*)d_in[5];
    const float* Wk = (const float*)d_in[6];
    const float* bk = (const float*)d_in[7];
    const float* Wv = (const float*)d_in[8];
    const float* bv = (const float*)d_in[9];
    const float* Wo = (const float*)d_in[10];
    const float* bo = (const float*)d_in[11];
    const float* gamma = (const float*)d_in[12];
    const float* beta  = (const float*)d_in[13];

    float* out  = (float*)d_out;
    float* attn = out + (size_t)BSROWS * EMB;

    __nv_bfloat16 *qh, *ql, *kh, *kl, *vh, *vl;
    float *ctxp, *xp;
    cudaGetSymbolAddress((void**)&qh, g_qh);
    cudaGetSymbolAddress((void**)&ql, g_ql);
    cudaGetSymbolAddress((void**)&kh, g_kh);
    cudaGetSymbolAddress((void**)&kl, g_kl);
    cudaGetSymbolAddress((void**)&vh, g_vh);
    cudaGetSymbolAddress((void**)&vl, g_vl);
    cudaGetSymbolAddress((void**)&ctxp, g_ctx);
    cudaGetSymbolAddress((void**)&xp,   g_x);

    cudaFuncSetAttribute(mma_scores, cudaFuncAttributeMaxDynamicSharedMemorySize,
                         SC_SMEM);

    dim3 gemm_grid(EMB / 64, BSROWS / 128);        // 8 x 64
    mma_gemm512<0><<<gemm_grid, 256>>>(Q, Wq, bq, nullptr, qh, ql, nullptr);
    mma_gemm512<0><<<gemm_grid, 256>>>(K, Wk, bk, nullptr, kh, kl, nullptr);
    mma_gemm512<0><<<gemm_grid, 256>>>(V, Wv, bv, nullptr, vh, vl, nullptr);

    dim3 sc_grid(SS / 64, SS / 128, BH);           // 32 x 16 x 32
    mma_scores<<<sc_grid, 256, SC_SMEM>>>(mask, attn);

    softmax_kernel<<<BH * SS, 256>>>(attn);

    dim3 ctx_grid(SS / 128, BH);                   // 16 x 32
    mma_context<<<ctx_grid, 256>>>(attn, ctxp);

    mma_gemm512<1><<<gemm_grid, 256>>>(ctxp, Wo, bo, Q, nullptr, nullptr, xp);

    ln_kernel<<<BSROWS, 128>>>(gamma, beta, out);
}